// round 10
// baseline (speedup 1.0000x reference)
#include <cuda_runtime.h>
#include <cuda_fp16.h>

#define NN 100000
#define EE 1600000
#define IN_F 128
#define OUT_F 64
#define HH 8
#define BKT 96   // slots per node; P(Poisson(16) >= 96) ~ 1e-40

// ---------------------------------------------------------------------------
// Device-global scratch (no allocations allowed; zero-initialized at load)
// ---------------------------------------------------------------------------
__device__ __half g_qh[NN * OUT_F];
__device__ __half g_kvh[NN * 128];     // per node: [0:64)=k, [64:128)=v fp16

__device__ uint4 g_wf4[192 * 4 * 4];   // W fp16 fragments, kb innermost (uint4 = 2 kb)
__device__ float g_bias[192];           // bq|bk|bv concatenated
__device__ volatile int g_flag;         // W-pack done flag (reset by agg tail)

__device__ int g_cnt[NN];               // per-src cursor (reset by agg tail)
__device__ int g_bkt[NN * BKT];         // dst indices bucketed by src

// packed fp32x2 helpers
#define PACK2(out, lo, hi) \
    asm("mov.b64 %0, {%1, %2};" : "=l"(out) : "f"(lo), "f"(hi))
#define FMA2(d, a, b, c) \
    asm("fma.rn.f32x2 %0, %1, %2, %3;" : "=l"(d) : "l"(a), "l"(b), "l"(c))
#define UNPACK2(lo, hi, in) \
    asm("mov.b64 {%0, %1}, %2;" : "=f"(lo), "=f"(hi) : "l"(in))

// ---------------------------------------------------------------------------
// K1: fused pack + scatter + GEMM in one grid.
//   block 0                     : pack W fragments + biases, set g_flag
//   blocks [1, 1+SCAT_B)        : edge bucket-scatter (2 edges/thread)
//   blocks [1+SCAT_B, ..)       : QKV tensor-core GEMM (spin on g_flag)
// ---------------------------------------------------------------------------
#define XS_LDH 136
#define GEMM_B ((NN + 63) / 64)            // 1563
#define SCAT_B (EE / (256 * 2))            // 3125 exact
#define GEMM_0 (1 + SCAT_B)

__global__ __launch_bounds__(256) void work_kernel(
    const float* __restrict__ x, const int* __restrict__ edge,
    const float* __restrict__ Wq, const float* __restrict__ bq,
    const float* __restrict__ Wk, const float* __restrict__ bk,
    const float* __restrict__ Wv, const float* __restrict__ bv)
{
    __shared__ __half Xs[64][XS_LDH];
    const int tid = threadIdx.x;

    if (blockIdx.x == 0) {
        // ---------------- pack W fragments + biases ----------------
        uint2* wf2 = reinterpret_cast<uint2*>(g_wf4);
#pragma unroll
        for (int i = 0; i < 24; i++) {
            int f = tid + 256 * i;          // 0..6143
            int kb = f & 7;
            int j  = (f >> 3) & 3;
            int n  = f >> 5;
            const float* Wr = (n < 64) ? (Wq + n * IN_F)
                            : (n < 128) ? (Wk + (n - 64) * IN_F)
                                        : (Wv + (n - 128) * IN_F);
            int k = kb * 16 + 2 * j;
            __half2 lo = __floats2half2_rn(Wr[k],     Wr[k + 1]);
            __half2 hi = __floats2half2_rn(Wr[k + 8], Wr[k + 9]);
            uint2 pk;
            pk.x = *reinterpret_cast<unsigned*>(&lo);
            pk.y = *reinterpret_cast<unsigned*>(&hi);
            wf2[f] = pk;
        }
        if (tid < 192)
            g_bias[tid] = (tid < 64) ? bq[tid] : (tid < 128) ? bk[tid - 64] : bv[tid - 128];
        __syncthreads();
        __threadfence();
        if (tid == 0) g_flag = 1;
        return;
    }

    if (blockIdx.x < GEMM_0) {
        // ---------------- scatter: 2 edges per thread ----------------
        int e = ((blockIdx.x - 1) * 256 + tid) * 2;
        int2 ss = *reinterpret_cast<const int2*>(&edge[e]);
        int2 dd = *reinterpret_cast<const int2*>(&edge[EE + e]);
        int p0 = atomicAdd(&g_cnt[ss.x], 1);
        if (p0 < BKT) g_bkt[ss.x * BKT + p0] = dd.x;
        int p1 = atomicAdd(&g_cnt[ss.y], 1);
        if (p1 < BKT) g_bkt[ss.y * BKT + p1] = dd.y;
        return;
    }

    // ---------------- GEMM ----------------
    const int w = tid >> 5, l = tid & 31;
    const int row0 = (blockIdx.x - GEMM_0) * 64;

    // load x tile first (independent of W pack)
    const float4* x4 = reinterpret_cast<const float4*>(x);
#pragma unroll
    for (int i = 0; i < 8; i++) {
        int idx = tid + 256 * i;
        int r = idx >> 5, c4 = idx & 31;
        int row = row0 + r;
        if (row >= NN) row = NN - 1;
        float4 v = x4[(size_t)row * 32 + c4];
        __half2 h0 = __floats2half2_rn(v.x, v.y);
        __half2 h1 = __floats2half2_rn(v.z, v.w);
        uint2 pk;
        pk.x = *reinterpret_cast<unsigned*>(&h0);
        pk.y = *reinterpret_cast<unsigned*>(&h1);
        *reinterpret_cast<uint2*>(&Xs[r][c4 * 4]) = pk;
    }

    // wait for W pack (bid 0 is always in wave 1; pack finishes in ~2us)
    if (tid == 0) { while (g_flag == 0) { } }
    __syncthreads();
    __threadfence();   // acquire: order g_wf4/g_bias reads after flag

    const int wm = w & 3;
    const int nh = w >> 2;
    const int m0 = wm * 16;
    const int g = l >> 2, j = l & 3;

    float c[12][4];
#pragma unroll
    for (int t = 0; t < 12; t++)
#pragma unroll
        for (int p = 0; p < 4; p++) c[t][p] = 0.f;

    const int sel = l >> 3;
    const int a_row = m0 + ((sel & 1) << 3) + (l & 7);
    const int a_col = (sel >> 1) << 3;

#pragma unroll
    for (int kb2 = 0; kb2 < 4; kb2++) {
        // two ldmatrix: kb = 2*kb2 and 2*kb2+1
        unsigned a0, a1, a2, a3, a4, a5, a6, a7;
        unsigned sa0 = (unsigned)__cvta_generic_to_shared(&Xs[a_row][(2 * kb2) * 16 + a_col]);
        unsigned sa1 = (unsigned)__cvta_generic_to_shared(&Xs[a_row][(2 * kb2 + 1) * 16 + a_col]);
        asm volatile("ldmatrix.sync.aligned.m8n8.x4.shared.b16 {%0,%1,%2,%3}, [%4];"
                     : "=r"(a0), "=r"(a1), "=r"(a2), "=r"(a3) : "r"(sa0));
        asm volatile("ldmatrix.sync.aligned.m8n8.x4.shared.b16 {%0,%1,%2,%3}, [%4];"
                     : "=r"(a4), "=r"(a5), "=r"(a6), "=r"(a7) : "r"(sa1));

#pragma unroll
        for (int t = 0; t < 12; t++) {
            int n = nh * 96 + t * 8 + g;
            uint4 bf = g_wf4[((n * 4 + j) * 8 + 2 * kb2) >> 1];   // frags for both kb
            asm volatile(
                "mma.sync.aligned.m16n8k16.row.col.f32.f16.f16.f32 "
                "{%0,%1,%2,%3}, {%4,%5,%6,%7}, {%8,%9}, {%0,%1,%2,%3};"
                : "+f"(c[t][0]), "+f"(c[t][1]), "+f"(c[t][2]), "+f"(c[t][3])
                : "r"(a0), "r"(a1), "r"(a2), "r"(a3), "r"(bf.x), "r"(bf.y));
            asm volatile(
                "mma.sync.aligned.m16n8k16.row.col.f32.f16.f16.f32 "
                "{%0,%1,%2,%3}, {%4,%5,%6,%7}, {%8,%9}, {%0,%1,%2,%3};"
                : "+f"(c[t][0]), "+f"(c[t][1]), "+f"(c[t][2]), "+f"(c[t][3])
                : "r"(a4), "r"(a5), "r"(a6), "r"(a7), "r"(bf.z), "r"(bf.w));
        }
    }

    // epilogue: q -> g_qh; k,v interleaved -> g_kvh
    const int r0g = row0 + m0 + g;
    const int r1g = r0g + 8;
#pragma unroll
    for (int t = 0; t < 12; t++) {
        int n = nh * 96 + t * 8 + 2 * j;
        float2 bb = *reinterpret_cast<const float2*>(&g_bias[n]);
        int m = n >> 6, col = n & 63;
        __half2 h0 = __floats2half2_rn(c[t][0] + bb.x, c[t][1] + bb.y);
        __half2 h1 = __floats2half2_rn(c[t][2] + bb.x, c[t][3] + bb.y);
        if (m == 0) {
            if (r0g < NN) *reinterpret_cast<__half2*>(&g_qh[(size_t)r0g * 64 + col]) = h0;
            if (r1g < NN) *reinterpret_cast<__half2*>(&g_qh[(size_t)r1g * 64 + col]) = h1;
        } else {
            int ofs = (m == 1) ? col : (64 + col);
            if (r0g < NN) *reinterpret_cast<__half2*>(&g_kvh[(size_t)r0g * 128 + ofs]) = h0;
            if (r1g < NN) *reinterpret_cast<__half2*>(&g_kvh[(size_t)r1g * 128 + ofs]) = h1;
        }
    }
}

// ---------------------------------------------------------------------------
// K2: aggregation.  Warp = 4 nodes; lane = (node_local, head); each lane owns
// the full (node, head) accumulator — no cross-lane reduction.  int4-batched
// bucket indices, HFMA2 score, single ex2.approx (scale folded), f32x2 accum.
// Tail resets g_cnt / g_flag for the next graph replay.
// ---------------------------------------------------------------------------
__global__ __launch_bounds__(256) void agg_kernel(float* __restrict__ out)
{
    const int gw = (blockIdx.x * 256 + threadIdx.x) >> 5;
    const int lane = threadIdx.x & 31;
    const int node = gw * 4 + (lane >> 3);   // exact: 3125*8*4 = 100000
    const int h = lane & 7;
    if (node >= NN) return;

    uint4 qv = *reinterpret_cast<const uint4*>(&g_qh[(size_t)node * 64 + h * 8]);
    const __half2* qp = reinterpret_cast<const __half2*>(&qv);

    int cnt = g_cnt[node];
    if (cnt > BKT) cnt = BKT;
    const int* bp = &g_bkt[node * BKT];

    float den = 0.f;
    unsigned long long acc0, acc1, acc2, acc3;
    PACK2(acc0, 0.f, 0.f);  PACK2(acc1, 0.f, 0.f);
    PACK2(acc2, 0.f, 0.f);  PACK2(acc3, 0.f, 0.f);

    for (int t4 = 0; t4 < cnt; t4 += 4) {
        int4 dd = *reinterpret_cast<const int4*>(&bp[t4]);
        int dts[4] = {dd.x, dd.y, dd.z, dd.w};
#pragma unroll
        for (int u = 0; u < 4; u++) {
            if (t4 + u < cnt) {
                const uint4* kvp = reinterpret_cast<const uint4*>(&g_kvh[(size_t)dts[u] * 128]);
                uint4 kv = kvp[h];        // k row (8 halves)
                uint4 vv = kvp[8 + h];    // v row (+128B immediate)

                const __half2* k2 = reinterpret_cast<const __half2*>(&kv);
                __half2 pr = __hmul2(qp[0], k2[0]);
                pr = __hfma2(qp[1], k2[1], pr);
                pr = __hfma2(qp[2], k2[2], pr);
                pr = __hfma2(qp[3], k2[3], pr);
                float s = __low2float(pr) + __high2float(pr);
                // exp(s/sqrt(8)) = 2^(s * 0.51011276)
                float ex;
                asm("ex2.approx.f32 %0, %1;" : "=f"(ex) : "f"(s * 0.5101127652f));
                den += ex;

                unsigned long long ex2r;
                PACK2(ex2r, ex, ex);
                const __half2* v2 = reinterpret_cast<const __half2*>(&vv);
                float2 f0 = __half22float2(v2[0]);
                float2 f1 = __half22float2(v2[1]);
                float2 f2 = __half22float2(v2[2]);
                float2 f3 = __half22float2(v2[3]);
                unsigned long long vp0, vp1, vp2, vp3;
                PACK2(vp0, f0.x, f0.y);  PACK2(vp1, f1.x, f1.y);
                PACK2(vp2, f2.x, f2.y);  PACK2(vp3, f3.x, f3.y);
                FMA2(acc0, ex2r, vp0, acc0);
                FMA2(acc1, ex2r, vp1, acc1);
                FMA2(acc2, ex2r, vp2, acc2);
                FMA2(acc3, ex2r, vp3, acc3);
            }
        }
    }

    float inv = 1.f / (den + 1e-16f);
    float o[8];
    UNPACK2(o[0], o[1], acc0);  UNPACK2(o[2], o[3], acc1);
    UNPACK2(o[4], o[5], acc2);  UNPACK2(o[6], o[7], acc3);

    float4 o0 = make_float4(o[0] * inv, o[1] * inv, o[2] * inv, o[3] * inv);
    float4 o1 = make_float4(o[4] * inv, o[5] * inv, o[6] * inv, o[7] * inv);
    float4* op = reinterpret_cast<float4*>(&out[(size_t)node * 64 + h * 8]);
    op[0] = o0;
    op[1] = o1;

    if (h == 0) g_cnt[node] = 0;                  // restore for next replay
    if (node == 0 && h == 1) g_flag = 0;          // reset pack flag
}

extern "C" void kernel_launch(void* const* d_in, const int* in_sizes, int n_in,
                              void* d_out, int out_size)
{
    const float* x    = (const float*)d_in[0];
    const int*   edge = (const int*)d_in[1];
    const float* Wq   = (const float*)d_in[2];
    const float* bq   = (const float*)d_in[3];
    const float* Wk   = (const float*)d_in[4];
    const float* bk   = (const float*)d_in[5];
    const float* Wv   = (const float*)d_in[6];
    const float* bv   = (const float*)d_in[7];
    float* out = (float*)d_out;

    work_kernel<<<1 + SCAT_B + GEMM_B, 256>>>(x, edge, Wq, bq, Wk, bk, Wv, bv);
    agg_kernel<<<NN / 32, 256>>>(out);   // 3125 blocks = 8 warps x 4 nodes
}

// round 11
// speedup vs baseline: 1.1483x; 1.1483x over previous
#include <cuda_runtime.h>
#include <cuda_fp16.h>

#define NN 100000
#define EE 1600000
#define IN_F 128
#define OUT_F 64
#define HH 8
#define BKT 96   // slots per node; P(Poisson(16) >= 96) ~ 1e-40

// ---------------------------------------------------------------------------
// Device-global scratch (no allocations allowed; zero-initialized at load)
// ---------------------------------------------------------------------------
__device__ __half g_qh[NN * OUT_F];
__device__ __half g_kvh[NN * 128];     // per node: [0:64)=k, [64:128)=v fp16

__device__ uint2 g_wf[192 * 8 * 4];    // W fp16, HMMA-B fragment order
__device__ float g_bias[192];           // bq|bk|bv concatenated

__device__ int g_cnt[NN];               // per-src cursor (reset by agg tail)
__device__ int g_bkt[NN * BKT];         // dst indices bucketed by src

// packed fp32x2 helpers
#define PACK2(out, lo, hi) \
    asm("mov.b64 %0, {%1, %2};" : "=l"(out) : "f"(lo), "f"(hi))
#define FMA2(d, a, b, c) \
    asm("fma.rn.f32x2 %0, %1, %2, %3;" : "=l"(d) : "l"(a), "l"(b), "l"(c))
#define UNPACK2(lo, hi, in) \
    asm("mov.b64 {%0, %1}, %2;" : "=f"(lo), "=f"(hi) : "l"(in))

// ---------------------------------------------------------------------------
// K0: pack W into HMMA fragment order + biases (tiny).
// ---------------------------------------------------------------------------
__global__ __launch_bounds__(256) void init_kernel(
    const float* __restrict__ Wq, const float* __restrict__ bq,
    const float* __restrict__ Wk, const float* __restrict__ bk,
    const float* __restrict__ Wv, const float* __restrict__ bv)
{
    int idx = blockIdx.x * blockDim.x + threadIdx.x;   // < 6144
    {
        int j  = idx & 3;
        int kb = (idx >> 2) & 7;
        int n  = idx >> 5;
        const float* Wr = (n < 64) ? (Wq + n * IN_F)
                        : (n < 128) ? (Wk + (n - 64) * IN_F)
                                    : (Wv + (n - 128) * IN_F);
        int k = kb * 16 + 2 * j;
        __half2 lo = __floats2half2_rn(Wr[k],     Wr[k + 1]);
        __half2 hi = __floats2half2_rn(Wr[k + 8], Wr[k + 9]);
        uint2 pk;
        pk.x = *reinterpret_cast<unsigned*>(&lo);
        pk.y = *reinterpret_cast<unsigned*>(&hi);
        g_wf[idx] = pk;
    }
    if (idx < 192) {
        g_bias[idx] = (idx < 64) ? bq[idx] : (idx < 128) ? bk[idx - 64] : bv[idx - 128];
    }
}

// ---------------------------------------------------------------------------
// K1: merged GEMM + scatter, roles INTERLEAVED by bid % 3 so both kinds run
// concurrently on every SM (scatter's atomic/store latency hides under the
// GEMM's tensor work).  grid = 4689: 1563 GEMM (bid%3==0), 3125 scatter.
// ---------------------------------------------------------------------------
#define XS_LDH 136
#define GEMM_B ((NN + 63) / 64)            // 1563
#define SCAT_B (EE / (256 * 2))            // 3125 exact
#define WORK_G (GEMM_B * 3)                // 4689 >= 1 + SCAT_B per role math

__global__ __launch_bounds__(256) void work_kernel(
    const float* __restrict__ x, const int* __restrict__ edge)
{
    __shared__ __half Xs[64][XS_LDH];
    const int tid = threadIdx.x;
    const unsigned bid = blockIdx.x;

    if (bid % 3u != 0u) {
        // ---------------- scatter: 2 edges per thread ----------------
        int sidx = (int)(bid - bid / 3u - 1u);     // 0..3125
        if (sidx >= SCAT_B) return;
        int e = (sidx * 256 + tid) * 2;
        int2 ss = *reinterpret_cast<const int2*>(&edge[e]);
        int2 dd = *reinterpret_cast<const int2*>(&edge[EE + e]);
        int p0 = atomicAdd(&g_cnt[ss.x], 1);
        if (p0 < BKT) g_bkt[ss.x * BKT + p0] = dd.x;
        int p1 = atomicAdd(&g_cnt[ss.y], 1);
        if (p1 < BKT) g_bkt[ss.y * BKT + p1] = dd.y;
        return;
    }

    // ---------------- GEMM ----------------
    const int w = tid >> 5, l = tid & 31;
    const int row0 = (int)(bid / 3u) * 64;

    const float4* x4 = reinterpret_cast<const float4*>(x);
#pragma unroll
    for (int i = 0; i < 8; i++) {
        int idx = tid + 256 * i;
        int r = idx >> 5, c4 = idx & 31;
        int row = row0 + r;
        if (row >= NN) row = NN - 1;
        float4 v = x4[(size_t)row * 32 + c4];
        __half2 h0 = __floats2half2_rn(v.x, v.y);
        __half2 h1 = __floats2half2_rn(v.z, v.w);
        uint2 pk;
        pk.x = *reinterpret_cast<unsigned*>(&h0);
        pk.y = *reinterpret_cast<unsigned*>(&h1);
        *reinterpret_cast<uint2*>(&Xs[r][c4 * 4]) = pk;
    }
    __syncthreads();

    const int wm = w & 3;
    const int nh = w >> 2;
    const int m0 = wm * 16;
    const int g = l >> 2, j = l & 3;

    float c[12][4];
#pragma unroll
    for (int t = 0; t < 12; t++)
#pragma unroll
        for (int p = 0; p < 4; p++) c[t][p] = 0.f;

    const int sel = l >> 3;
    const int a_row = m0 + ((sel & 1) << 3) + (l & 7);
    const int a_col = (sel >> 1) << 3;

#pragma unroll
    for (int kb = 0; kb < 8; kb++) {
        unsigned a0, a1, a2, a3;
        unsigned sa = (unsigned)__cvta_generic_to_shared(&Xs[a_row][kb * 16 + a_col]);
        asm volatile("ldmatrix.sync.aligned.m8n8.x4.shared.b16 {%0,%1,%2,%3}, [%4];"
                     : "=r"(a0), "=r"(a1), "=r"(a2), "=r"(a3) : "r"(sa));

        uint2 bfr[12];
#pragma unroll
        for (int t = 0; t < 12; t++) {
            int n = nh * 96 + t * 8 + g;
            bfr[t] = g_wf[(n * 8 + kb) * 4 + j];
        }
#pragma unroll
        for (int t = 0; t < 12; t++) {
            asm volatile(
                "mma.sync.aligned.m16n8k16.row.col.f32.f16.f16.f32 "
                "{%0,%1,%2,%3}, {%4,%5,%6,%7}, {%8,%9}, {%0,%1,%2,%3};"
                : "+f"(c[t][0]), "+f"(c[t][1]), "+f"(c[t][2]), "+f"(c[t][3])
                : "r"(a0), "r"(a1), "r"(a2), "r"(a3), "r"(bfr[t].x), "r"(bfr[t].y));
        }
    }

    // epilogue: q -> g_qh; k,v interleaved -> g_kvh
    const int r0g = row0 + m0 + g;
    const int r1g = r0g + 8;
#pragma unroll
    for (int t = 0; t < 12; t++) {
        int n = nh * 96 + t * 8 + 2 * j;
        float2 bb = *reinterpret_cast<const float2*>(&g_bias[n]);
        int m = n >> 6, col = n & 63;
        __half2 h0 = __floats2half2_rn(c[t][0] + bb.x, c[t][1] + bb.y);
        __half2 h1 = __floats2half2_rn(c[t][2] + bb.x, c[t][3] + bb.y);
        if (m == 0) {
            if (r0g < NN) *reinterpret_cast<__half2*>(&g_qh[(size_t)r0g * 64 + col]) = h0;
            if (r1g < NN) *reinterpret_cast<__half2*>(&g_qh[(size_t)r1g * 64 + col]) = h1;
        } else {
            int ofs = (m == 1) ? col : (64 + col);
            if (r0g < NN) *reinterpret_cast<__half2*>(&g_kvh[(size_t)r0g * 128 + ofs]) = h0;
            if (r1g < NN) *reinterpret_cast<__half2*>(&g_kvh[(size_t)r1g * 128 + ofs]) = h1;
        }
    }
}

// ---------------------------------------------------------------------------
// K2: aggregation.  Warp = 4 nodes; lane = (node_local, head); each lane owns
// the full (node, head) accumulator.  Unconditional quads + scalar remainder;
// HFMA2 score; single ex2.approx (1/sqrt(8)*log2e folded); f32x2 accumulate.
// ---------------------------------------------------------------------------
__device__ __forceinline__ void agg_edge(
    int dst, int h, const __half2* qp,
    float& den,
    unsigned long long& acc0, unsigned long long& acc1,
    unsigned long long& acc2, unsigned long long& acc3)
{
    const uint4* kvp = reinterpret_cast<const uint4*>(&g_kvh[(size_t)dst * 128]);
    uint4 kv = kvp[h];        // k row (8 halves)
    uint4 vv = kvp[8 + h];    // v row (+128B)

    const __half2* k2 = reinterpret_cast<const __half2*>(&kv);
    __half2 pr = __hmul2(qp[0], k2[0]);
    pr = __hfma2(qp[1], k2[1], pr);
    pr = __hfma2(qp[2], k2[2], pr);
    pr = __hfma2(qp[3], k2[3], pr);
    float s = __low2float(pr) + __high2float(pr);
    float ex;
    asm("ex2.approx.f32 %0, %1;" : "=f"(ex) : "f"(s * 0.5101127652f));
    den += ex;

    unsigned long long ex2r;
    PACK2(ex2r, ex, ex);
    const __half2* v2 = reinterpret_cast<const __half2*>(&vv);
    float2 f0 = __half22float2(v2[0]);
    float2 f1 = __half22float2(v2[1]);
    float2 f2 = __half22float2(v2[2]);
    float2 f3 = __half22float2(v2[3]);
    unsigned long long vp0, vp1, vp2, vp3;
    PACK2(vp0, f0.x, f0.y);  PACK2(vp1, f1.x, f1.y);
    PACK2(vp2, f2.x, f2.y);  PACK2(vp3, f3.x, f3.y);
    FMA2(acc0, ex2r, vp0, acc0);
    FMA2(acc1, ex2r, vp1, acc1);
    FMA2(acc2, ex2r, vp2, acc2);
    FMA2(acc3, ex2r, vp3, acc3);
}

__global__ __launch_bounds__(256) void agg_kernel(float* __restrict__ out)
{
    const int gw = (blockIdx.x * 256 + threadIdx.x) >> 5;
    const int lane = threadIdx.x & 31;
    const int node = gw * 4 + (lane >> 3);   // exact: 3125*8*4 = 100000
    const int h = lane & 7;
    if (node >= NN) return;

    uint4 qv = *reinterpret_cast<const uint4*>(&g_qh[(size_t)node * 64 + h * 8]);
    const __half2* qp = reinterpret_cast<const __half2*>(&qv);

    int cnt = g_cnt[node];
    if (cnt > BKT) cnt = BKT;
    const int* bp = &g_bkt[node * BKT];

    float den = 0.f;
    unsigned long long acc0, acc1, acc2, acc3;
    PACK2(acc0, 0.f, 0.f);  PACK2(acc1, 0.f, 0.f);
    PACK2(acc2, 0.f, 0.f);  PACK2(acc3, 0.f, 0.f);

    const int full = cnt & ~3;
    for (int t4 = 0; t4 < full; t4 += 4) {
        int4 dd = *reinterpret_cast<const int4*>(&bp[t4]);
        agg_edge(dd.x, h, qp, den, acc0, acc1, acc2, acc3);
        agg_edge(dd.y, h, qp, den, acc0, acc1, acc2, acc3);
        agg_edge(dd.z, h, qp, den, acc0, acc1, acc2, acc3);
        agg_edge(dd.w, h, qp, den, acc0, acc1, acc2, acc3);
    }
    for (int t = full; t < cnt; t++)
        agg_edge(bp[t], h, qp, den, acc0, acc1, acc2, acc3);

    float inv = 1.f / (den + 1e-16f);
    float o[8];
    UNPACK2(o[0], o[1], acc0);  UNPACK2(o[2], o[3], acc1);
    UNPACK2(o[4], o[5], acc2);  UNPACK2(o[6], o[7], acc3);

    float4 o0 = make_float4(o[0] * inv, o[1] * inv, o[2] * inv, o[3] * inv);
    float4 o1 = make_float4(o[4] * inv, o[5] * inv, o[6] * inv, o[7] * inv);
    float4* op = reinterpret_cast<float4*>(&out[(size_t)node * 64 + h * 8]);
    op[0] = o0;
    op[1] = o1;

    if (h == 0) g_cnt[node] = 0;   // restore invariant for next replay
}

extern "C" void kernel_launch(void* const* d_in, const int* in_sizes, int n_in,
                              void* d_out, int out_size)
{
    const float* x    = (const float*)d_in[0];
    const int*   edge = (const int*)d_in[1];
    const float* Wq   = (const float*)d_in[2];
    const float* bq   = (const float*)d_in[3];
    const float* Wk   = (const float*)d_in[4];
    const float* bk   = (const float*)d_in[5];
    const float* Wv   = (const float*)d_in[6];
    const float* bv   = (const float*)d_in[7];
    float* out = (float*)d_out;

    init_kernel<<<24, 256>>>(Wq, bq, Wk, bk, Wv, bv);
    work_kernel<<<WORK_G, 256>>>(x, edge);
    agg_kernel<<<NN / 32, 256>>>(out);   // 3125 blocks = 8 warps x 4 nodes
}